// round 8
// baseline (speedup 1.0000x reference)
#include <cuda_runtime.h>
#include <cuda_fp16.h>
#include <cstdint>

// BinaryConv2d via Winograd F(2x2,3x3) + mma.sync HMMA, fp16 data, fp32 accum.
// out[n,o,h,w] = sum_{c,kh,kw} x[n,c,h+kh-1,w+kw-1]*sign(W[o,c,kh,kw]) + bias[o]
// 16 elementwise GEMMs M=25088 tiles, N=256, K=128; inverse transform fused in regs.

#define NB 32
#define CI 128
#define CO 256
#define HH 56
#define HP 58
#define PIXN (HH*HH)
#define TPI  784              // 28*28 tiles per image
#define NTILE (NB*TPI)        // 25088
#define NITER 32              // 16 xi-nu * 2 chunks of k=64
#define STAGES 4

// padded NHWC fp16
__device__ __half g_xp[(size_t)NB*HP*HP*128];
// Winograd-transformed input U[xi*4+nu][tile][c]
__device__ __half g_u[(size_t)16*NTILE*128];
// Winograd-transformed binarized weights V[xi*4+nu][oc][c]
__device__ __half g_v[(size_t)16*CO*128];

// ---------------- stage 1: pad + fp16 ----------------
__global__ __launch_bounds__(256)
void transform_x_kernel(const float* __restrict__ x) {
    __shared__ float s[128][57];
    const int hp = blockIdx.x % HP;
    const int n  = blockIdx.x / HP;
    const int tid = threadIdx.x;
    const bool interior_h = (hp >= 1 && hp <= HH);

    if (interior_h) {
        const int h = hp - 1;
        const float* src = x + ((size_t)n * CI * HH + h) * HH;
        for (int idx = tid; idx < CI * HH; idx += 256) {
            int c = idx / HH, w = idx - (idx / HH) * HH;
            s[c][w] = src[(size_t)c * PIXN + w];
        }
    }
    __syncthreads();

    const int c  = tid & 127;
    const int wh = tid >> 7;
    __half* ob = g_xp + ((size_t)(n * HP + hp) * HP) * 128 + c;
#pragma unroll 4
    for (int wp = wh * 29; wp < wh * 29 + 29; wp++) {
        float v = 0.0f;
        if (interior_h && wp >= 1 && wp <= HH) v = s[c][wp - 1];
        ob[(size_t)wp * 128] = __float2half_rn(v);
    }
}

// ---------------- stage 2: input Winograd transform ----------------
__global__ __launch_bounds__(256)
void winograd_x_kernel() {
    int idx = blockIdx.x * 256 + threadIdx.x;    // over NTILE*128
    int c = idx & 127;
    int t = idx >> 7;
    int n  = t / TPI;
    int r  = t - n * TPI;
    int ti = r / 28, tj = r - (r / 28) * 28;

    const __half* base = g_xp + ((size_t)(n * HP + 2 * ti) * HP + 2 * tj) * 128 + c;
    float d[4][4];
#pragma unroll
    for (int i = 0; i < 4; i++)
#pragma unroll
        for (int s = 0; s < 4; s++)
            d[i][s] = __half2float(base[(size_t)(i * HP + s) * 128]);

    float tr[4][4];
#pragma unroll
    for (int s = 0; s < 4; s++) {
        tr[0][s] = d[0][s] - d[2][s];
        tr[1][s] = d[1][s] + d[2][s];
        tr[2][s] = d[2][s] - d[1][s];
        tr[3][s] = d[1][s] - d[3][s];
    }
    float u[4][4];
#pragma unroll
    for (int i = 0; i < 4; i++) {
        u[i][0] = tr[i][0] - tr[i][2];
        u[i][1] = tr[i][1] + tr[i][2];
        u[i][2] = tr[i][2] - tr[i][1];
        u[i][3] = tr[i][1] - tr[i][3];
    }
#pragma unroll
    for (int xi = 0; xi < 4; xi++)
#pragma unroll
        for (int nu = 0; nu < 4; nu++)
            g_u[((size_t)(xi * 4 + nu) * NTILE + t) * 128 + c] = __float2half_rn(u[xi][nu]);
}

// ---------------- stage 3: weight Winograd transform ----------------
__global__ __launch_bounds__(256)
void winograd_w_kernel(const float* __restrict__ w) {
    int idx = blockIdx.x * 256 + threadIdx.x;    // over CO*CI
    if (idx >= CO * CI) return;
    int oc = idx >> 7;
    int c  = idx & 127;
    float g[3][3];
#pragma unroll
    for (int r = 0; r < 3; r++)
#pragma unroll
        for (int s = 0; s < 3; s++)
            g[r][s] = (w[((size_t)(oc * CI + c)) * 9 + r * 3 + s] >= 0.0f) ? 1.0f : -1.0f;
    float gg[4][3];
#pragma unroll
    for (int s = 0; s < 3; s++) {
        gg[0][s] = g[0][s];
        gg[1][s] = 0.5f * (g[0][s] + g[1][s] + g[2][s]);
        gg[2][s] = 0.5f * (g[0][s] - g[1][s] + g[2][s]);
        gg[3][s] = g[2][s];
    }
#pragma unroll
    for (int i = 0; i < 4; i++) {
        float v0 = gg[i][0];
        float v1 = 0.5f * (gg[i][0] + gg[i][1] + gg[i][2]);
        float v2 = 0.5f * (gg[i][0] - gg[i][1] + gg[i][2]);
        float v3 = gg[i][2];
        g_v[((size_t)(i * 4 + 0) * CO + oc) * 128 + c] = __float2half_rn(v0);
        g_v[((size_t)(i * 4 + 1) * CO + oc) * 128 + c] = __float2half_rn(v1);
        g_v[((size_t)(i * 4 + 2) * CO + oc) * 128 + c] = __float2half_rn(v2);
        g_v[((size_t)(i * 4 + 3) * CO + oc) * 128 + c] = __float2half_rn(v3);
    }
}

// ---------------- main kernel ----------------
__device__ __forceinline__ uint32_t smem_u32(const void* p) {
    uint32_t a;
    asm("{ .reg .u64 t; cvta.to.shared.u64 t, %1; cvt.u32.u64 %0, t; }" : "=r"(a) : "l"(p));
    return a;
}
__device__ __forceinline__ void cp16(uint32_t dst, const void* src) {
    asm volatile("cp.async.cg.shared.global [%0], [%1], 16;" :: "r"(dst), "l"(src));
}
#define CP_COMMIT() asm volatile("cp.async.commit_group;" ::: "memory")
#define CP_WAIT2()  asm volatile("cp.async.wait_group 2;" ::: "memory")

__device__ __forceinline__ void ldsm4(uint32_t* r, uint32_t addr) {
    asm volatile("ldmatrix.sync.aligned.m8n8.x4.shared.b16 {%0,%1,%2,%3}, [%4];"
        : "=r"(r[0]), "=r"(r[1]), "=r"(r[2]), "=r"(r[3]) : "r"(addr));
}
__device__ __forceinline__ void mma16816(float* c, const uint32_t* a, uint32_t b0, uint32_t b1) {
    asm volatile("mma.sync.aligned.m16n8k16.row.col.f32.f16.f16.f32 "
        "{%0,%1,%2,%3}, {%4,%5,%6,%7}, {%8,%9}, {%0,%1,%2,%3};"
        : "+f"(c[0]), "+f"(c[1]), "+f"(c[2]), "+f"(c[3])
        : "r"(a[0]), "r"(a[1]), "r"(a[2]), "r"(a[3]), "r"(b0), "r"(b1));
}

#define A_ST  8192                   // 64 tiles x 64 k x fp16
#define B_ST  16384                  // 128 oc  x 64 k x fp16
#define ST_BYTES (A_ST + B_ST)       // 24 KB / stage
#define SMEM_SZ (STAGES * ST_BYTES)  // 96 KB

// inverse-transform row coefficients: A^T rows
__device__ const float c_AT[2][4] = {{1.f, 1.f, 1.f, 0.f}, {0.f, 1.f, -1.f, -1.f}};

__global__ __launch_bounds__(256, 1)
void binconv_wino_kernel(const float* __restrict__ bias, float* __restrict__ out) {
    extern __shared__ char smem[];
    const uint32_t sb = smem_u32(smem);

    const int tid  = threadIdx.x;
    const int wid  = tid >> 5;
    const int lane = tid & 31;
    const int t0   = blockIdx.x * 64;      // tile block
    const int ocb  = blockIdx.y * 128;     // oc block

    // ---- producer addressing ----
    const int arow = tid >> 3;             // 0..31 (tile within first 32) ; +32 via j
    const int seg  = tid & 7;
    // A unit u = tid + j*256: tile = arow + j*32, seg
    const uint32_t adst0 = sb + (uint32_t)(seg * 64 + arow) * 16;    // + j*32*16
    // B unit u = tid + j*256: oc = arow + j*32, seg
    const uint32_t bdst0 = sb + A_ST + (uint32_t)(seg * 128 + arow) * 16;

    // warp tiling: 2 (tiles) x 4 (oc); warp tile 32 tiles x 32 oc
    const int wm = (wid & 1) * 32;
    const int wn = (wid >> 1) * 32;

    float Y[4][2][4][4];                   // [ij][mi][nb][e]
#pragma unroll
    for (int ij = 0; ij < 4; ij++)
#pragma unroll
        for (int mi = 0; mi < 2; mi++)
#pragma unroll
            for (int nb = 0; nb < 4; nb++)
#pragma unroll
                for (int e = 0; e < 4; e++) Y[ij][mi][nb][e] = 0.0f;

    float macc[2][4][4];
#pragma unroll
    for (int mi = 0; mi < 2; mi++)
#pragma unroll
        for (int nb = 0; nb < 4; nb++)
#pragma unroll
            for (int e = 0; e < 4; e++) macc[mi][nb][e] = 0.0f;

    auto issue = [&](int kk) {
        if (kk < NITER) {
            const uint32_t soff = (uint32_t)(kk % STAGES) * ST_BYTES;
            const int xn  = kk >> 1;       // xi*4+nu
            const int sub = kk & 1;
            const __half* ua = g_u + ((size_t)xn * NTILE + t0 + arow) * 128 + sub * 64 + seg * 8;
#pragma unroll
            for (int j = 0; j < 2; j++)
                cp16(adst0 + j * 512 + soff, ua + (size_t)j * 32 * 128);
            const __half* vb = g_v + ((size_t)xn * CO + ocb + arow) * 128 + sub * 64 + seg * 8;
#pragma unroll
            for (int j = 0; j < 4; j++)
                cp16(bdst0 + j * 512 + soff, vb + (size_t)j * 32 * 128);
        }
        CP_COMMIT();
    };

    issue(0); issue(1); issue(2);

    const uint32_t a_lrow = (uint32_t)((lane >> 4) * 64 + (lane & 15)) * 16;
    const uint32_t b_lrow = (uint32_t)(((lane >> 3) & 1) * 128 + (lane & 7) + ((lane >> 4) << 3)) * 16;

    for (int kk = 0; kk < NITER; kk++) {
        const uint32_t soff = (uint32_t)(kk % STAGES) * ST_BYTES;
        CP_WAIT2();
        __syncthreads();
        issue(kk + 3);

#pragma unroll
        for (int kb = 0; kb < 4; kb++) {
            uint32_t af[2][4], bf[2][4];
#pragma unroll
            for (int mi = 0; mi < 2; mi++)
                ldsm4(af[mi], sb + soff + kb * 2048 + a_lrow + (uint32_t)(wm + mi * 16) * 16);
#pragma unroll
            for (int nj = 0; nj < 2; nj++)
                ldsm4(bf[nj], sb + A_ST + soff + kb * 4096 + b_lrow + (uint32_t)(wn + nj * 16) * 16);
#pragma unroll
            for (int mi = 0; mi < 2; mi++)
#pragma unroll
                for (int nb = 0; nb < 4; nb++) {
                    const uint32_t* bp = bf[nb >> 1];
                    if (nb & 1) mma16816(macc[mi][nb], af[mi], bp[2], bp[3]);
                    else        mma16816(macc[mi][nb], af[mi], bp[0], bp[1]);
                }
        }

        if (kk & 1) {
            // fold M[xi][nu] into Y with A^T coefficients, then clear macc
            const int xn = kk >> 1;
            const int xi = xn >> 2, nu = xn & 3;
#pragma unroll
            for (int i = 0; i < 2; i++) {
                const float fi = c_AT[i][xi];
                if (fi != 0.0f) {
#pragma unroll
                    for (int j = 0; j < 2; j++) {
                        const float f = fi * c_AT[j][nu];
                        if (f != 0.0f) {
#pragma unroll
                            for (int mi = 0; mi < 2; mi++)
#pragma unroll
                                for (int nb = 0; nb < 4; nb++)
#pragma unroll
                                    for (int e = 0; e < 4; e++)
                                        Y[i * 2 + j][mi][nb][e] = fmaf(f, macc[mi][nb][e], Y[i * 2 + j][mi][nb][e]);
                        }
                    }
                }
            }
#pragma unroll
            for (int mi = 0; mi < 2; mi++)
#pragma unroll
                for (int nb = 0; nb < 4; nb++)
#pragma unroll
                    for (int e = 0; e < 4; e++) macc[mi][nb][e] = 0.0f;
        }
    }

    // ---------------- epilogue: inverse-transformed outputs -> NCHW + bias ----------------
    const int qr  = lane >> 2;             // 0..7
    const int oc2 = (lane & 3) * 2;

    float2 bv[4];
#pragma unroll
    for (int nb = 0; nb < 4; nb++)
        bv[nb] = *(const float2*)(bias + ocb + wn + nb * 8 + oc2);

#pragma unroll
    for (int mi = 0; mi < 2; mi++) {
#pragma unroll
        for (int rh = 0; rh < 2; rh++) {
            const int t  = t0 + wm + mi * 16 + rh * 8 + qr;
            const int n2 = t / TPI;
            const int rr = t - n2 * TPI;
            const int ti = rr / 28;
            const int tj = rr - ti * 28;
            float* ob0 = out + ((size_t)n2 * CO) * PIXN + (size_t)(2 * ti) * HH + 2 * tj;
#pragma unroll
            for (int i = 0; i < 2; i++) {
#pragma unroll
                for (int j = 0; j < 2; j++) {
                    float* ob = ob0 + i * HH + j;
#pragma unroll
                    for (int nb = 0; nb < 4; nb++) {
                        const int oc = wn + nb * 8 + oc2;
                        ob[(size_t)(ocb + oc) * PIXN]     = Y[i * 2 + j][mi][nb][rh * 2 + 0] + bv[nb].x;
                        ob[(size_t)(ocb + oc + 1) * PIXN] = Y[i * 2 + j][mi][nb][rh * 2 + 1] + bv[nb].y;
                    }
                }
            }
        }
    }
}

// ---------------- launch ----------------
extern "C" void kernel_launch(void* const* d_in, const int* in_sizes, int n_in,
                              void* d_out, int out_size) {
    const float* x      = (const float*)d_in[0];
    const float* weight = (const float*)d_in[1];
    const float* bias   = (const float*)d_in[2];
    float* out          = (float*)d_out;

    cudaFuncSetAttribute(binconv_wino_kernel,
                         cudaFuncAttributeMaxDynamicSharedMemorySize, SMEM_SZ);

    transform_x_kernel<<<NB * HP, 256>>>(x);
    winograd_x_kernel<<<NTILE * 128 / 256, 256>>>();
    winograd_w_kernel<<<(CO * CI + 255) / 256, 256>>>(weight);

    dim3 grid(NTILE / 64, 2);
    binconv_wino_kernel<<<grid, 256, SMEM_SZ>>>(bias, out);
}